// round 1
// baseline (speedup 1.0000x reference)
#include <cuda_runtime.h>
#include <math.h>

// Problem constants (fixed by the dataset)
#define N_NODES 50000
#define E_EDGES 800000
#define E_TOT   (E_EDGES + N_NODES)

// ---------------- scratch (static __device__ allocations only) ----------------
__device__ float g_h1 [(size_t)N_NODES * 128];   // x @ W1            [N,4,32]
__device__ float g_h1a[(size_t)N_NODES * 128];   // elu(gat1 output)  [N,128]
__device__ float g_h2 [(size_t)N_NODES * 256];   // h1a @ W2          [N,8,32]
__device__ float g_as1[N_NODES * 4];
__device__ float g_ad1[N_NODES * 4];
__device__ float g_as2[N_NODES * 8];
__device__ float g_ad2[N_NODES * 8];
__device__ int   g_cnt[N_NODES];
__device__ int   g_rowptr[N_NODES + 1];
__device__ int   g_cursor[N_NODES];
__device__ int   g_col[E_TOT];
__device__ int   g_is64;

// ---------------- dtype detection for edge_index (int64 vs int32) -------------
__global__ void detect64_kernel(const unsigned int* __restrict__ w) {
    __shared__ int any;
    if (threadIdx.x == 0) any = 0;
    __syncthreads();
    // If int64 (little-endian) with values < 2^31, all odd words are 0.
    for (int i = 1 + 2 * threadIdx.x; i < 2048; i += 2 * blockDim.x)
        if (w[i] != 0u) any = 1;   // benign race
    __syncthreads();
    if (threadIdx.x == 0) g_is64 = (any == 0) ? 1 : 0;
}

__global__ void zero_cnt_kernel() {
    int i = blockIdx.x * blockDim.x + threadIdx.x;
    if (i < N_NODES) g_cnt[i] = 0;
}

__global__ void count_kernel(const void* __restrict__ ei) {
    int e = blockIdx.x * blockDim.x + threadIdx.x;
    if (e >= E_TOT) return;
    int dst;
    if (e < E_EDGES) {
        if (g_is64) dst = (int)((const long long*)ei)[(size_t)E_EDGES + e];
        else        dst = ((const int*)ei)[E_EDGES + e];
    } else {
        dst = e - E_EDGES;   // self loop
    }
    atomicAdd(&g_cnt[dst], 1);
}

// Single-block chunked inclusive scan -> rowptr + cursor
__global__ void scan_kernel() {
    __shared__ int sh[1024];
    __shared__ int carry;
    int tid = threadIdx.x;
    if (tid == 0) { carry = 0; g_rowptr[0] = 0; }
    __syncthreads();
    for (int base = 0; base < N_NODES; base += 1024) {
        int i = base + tid;
        int v = (i < N_NODES) ? g_cnt[i] : 0;
        sh[tid] = v;
        __syncthreads();
        for (int off = 1; off < 1024; off <<= 1) {
            int t = (tid >= off) ? sh[tid - off] : 0;
            __syncthreads();
            sh[tid] += t;
            __syncthreads();
        }
        int incl = sh[tid];
        int c = carry;
        if (i < N_NODES) {
            g_rowptr[i + 1] = c + incl;
            g_cursor[i]     = c + incl - v;
        }
        __syncthreads();
        if (tid == 1023) carry = c + incl;
        __syncthreads();
    }
}

__global__ void scatter_kernel(const void* __restrict__ ei) {
    int e = blockIdx.x * blockDim.x + threadIdx.x;
    if (e >= E_TOT) return;
    int src, dst;
    if (e < E_EDGES) {
        if (g_is64) {
            const long long* p = (const long long*)ei;
            src = (int)p[e];
            dst = (int)p[(size_t)E_EDGES + e];
        } else {
            const int* p = (const int*)ei;
            src = p[e];
            dst = p[E_EDGES + e];
        }
    } else {
        src = dst = e - E_EDGES;
    }
    int pos = atomicAdd(&g_cursor[dst], 1);
    g_col[pos] = src;
}

// ---------------- SGEMM: C[M,Ncols] = A[M,K] @ B[K,Ncols] ---------------------
// 64x64 tile, 256 threads, 4x4 per-thread register tile, BK=16.
#define BM 64
#define BN 64
#define BK 16
__global__ void sgemm_kernel(const float* __restrict__ A,
                             const float* __restrict__ B,
                             float* __restrict__ C,
                             int M, int Ncols, int K) {
    __shared__ float As[BK][BM];
    __shared__ float Bs[BK][BN];
    int tid = threadIdx.x;
    int row0 = blockIdx.y * BM;
    int col0 = blockIdx.x * BN;
    int ty = tid / 16, tx = tid % 16;

    int arow = tid / 4;          // 0..63
    int acol = (tid % 4) * 4;    // 0,4,8,12
    int brw  = tid / 16;         // 0..15
    int bcl  = (tid % 16) * 4;   // 0..60

    float acc[4][4];
#pragma unroll
    for (int i = 0; i < 4; i++)
#pragma unroll
        for (int j = 0; j < 4; j++) acc[i][j] = 0.f;

    for (int k0 = 0; k0 < K; k0 += BK) {
        float4 av = make_float4(0.f, 0.f, 0.f, 0.f);
        if (row0 + arow < M)
            av = *(const float4*)(A + (size_t)(row0 + arow) * K + k0 + acol);
        As[acol + 0][arow] = av.x;
        As[acol + 1][arow] = av.y;
        As[acol + 2][arow] = av.z;
        As[acol + 3][arow] = av.w;
        float4 bv = *(const float4*)(B + (size_t)(k0 + brw) * Ncols + col0 + bcl);
        *(float4*)&Bs[brw][bcl] = bv;
        __syncthreads();
#pragma unroll
        for (int kk = 0; kk < BK; kk++) {
            float4 a = *(float4*)&As[kk][ty * 4];
            float4 b = *(float4*)&Bs[kk][tx * 4];
            acc[0][0] += a.x * b.x; acc[0][1] += a.x * b.y; acc[0][2] += a.x * b.z; acc[0][3] += a.x * b.w;
            acc[1][0] += a.y * b.x; acc[1][1] += a.y * b.y; acc[1][2] += a.y * b.z; acc[1][3] += a.y * b.w;
            acc[2][0] += a.z * b.x; acc[2][1] += a.z * b.y; acc[2][2] += a.z * b.z; acc[2][3] += a.z * b.w;
            acc[3][0] += a.w * b.x; acc[3][1] += a.w * b.y; acc[3][2] += a.w * b.z; acc[3][3] += a.w * b.w;
        }
        __syncthreads();
    }
#pragma unroll
    for (int i = 0; i < 4; i++) {
        int r = row0 + ty * 4 + i;
        if (r < M)
            *(float4*)(C + (size_t)r * Ncols + col0 + tx * 4) =
                make_float4(acc[i][0], acc[i][1], acc[i][2], acc[i][3]);
    }
}

// ---------------- per-node attention coefficients -----------------------------
template <int H>
__global__ void alpha_kernel(const float* __restrict__ h,
                             const float* __restrict__ att_s,
                             const float* __restrict__ att_d,
                             float* __restrict__ as_out,
                             float* __restrict__ ad_out) {
    int idx = blockIdx.x * blockDim.x + threadIdx.x;
    if (idx >= N_NODES * H) return;
    int node = idx / H, hh = idx % H;
    const float* hp = h + (size_t)node * H * 32 + hh * 32;
    const float* a1 = att_s + hh * 32;
    const float* a2 = att_d + hh * 32;
    float s1 = 0.f, s2 = 0.f;
#pragma unroll
    for (int c = 0; c < 32; c += 4) {
        float4 v  = *(const float4*)(hp + c);
        float4 w1 = *(const float4*)(a1 + c);
        float4 w2 = *(const float4*)(a2 + c);
        s1 += v.x * w1.x + v.y * w1.y + v.z * w1.z + v.w * w1.w;
        s2 += v.x * w2.x + v.y * w2.y + v.z * w2.z + v.w * w2.w;
    }
    as_out[idx] = s1;
    ad_out[idx] = s2;
}

// ---------------- GAT edge aggregation: one warp per destination node ---------
// Channels C=32 map to lanes; heads H map to the per-lane register index.
template <int H, bool ELU_OUT, bool MEAN_OUT>
__global__ void gat_edge_kernel(const float* __restrict__ hfeat,
                                const float* __restrict__ asrc,
                                const float* __restrict__ adst,
                                const float* __restrict__ bias,
                                float* __restrict__ out) {
    int w    = (blockIdx.x * blockDim.x + threadIdx.x) >> 5;
    int lane = threadIdx.x & 31;
    if (w >= N_NODES) return;
    int beg = g_rowptr[w], end = g_rowptr[w + 1];

    float ad[H];
#pragma unroll
    for (int h = 0; h < H; h++) ad[h] = adst[(size_t)w * H + h];

    // pass 1: max over edges (lane-parallel)
    float m[H];
#pragma unroll
    for (int h = 0; h < H; h++) m[h] = -1e30f;
    for (int e = beg + lane; e < end; e += 32) {
        int src = g_col[e];
        const float4* ap4 = (const float4*)(asrc + (size_t)src * H);
        float av[H];
#pragma unroll
        for (int q = 0; q < H / 4; q++) {
            float4 t = ap4[q];
            av[4 * q] = t.x; av[4 * q + 1] = t.y; av[4 * q + 2] = t.z; av[4 * q + 3] = t.w;
        }
#pragma unroll
        for (int h = 0; h < H; h++) {
            float x = av[h] + ad[h];
            x = x > 0.f ? x : 0.2f * x;
            m[h] = fmaxf(m[h], x);
        }
    }
#pragma unroll
    for (int h = 0; h < H; h++)
#pragma unroll
        for (int off = 16; off; off >>= 1)
            m[h] = fmaxf(m[h], __shfl_xor_sync(0xffffffffu, m[h], off));

    // pass 2: softmax denominator
    float s[H];
#pragma unroll
    for (int h = 0; h < H; h++) s[h] = 0.f;
    for (int e = beg + lane; e < end; e += 32) {
        int src = g_col[e];
        const float4* ap4 = (const float4*)(asrc + (size_t)src * H);
        float av[H];
#pragma unroll
        for (int q = 0; q < H / 4; q++) {
            float4 t = ap4[q];
            av[4 * q] = t.x; av[4 * q + 1] = t.y; av[4 * q + 2] = t.z; av[4 * q + 3] = t.w;
        }
#pragma unroll
        for (int h = 0; h < H; h++) {
            float x = av[h] + ad[h];
            x = x > 0.f ? x : 0.2f * x;
            s[h] += __expf(x - m[h]);
        }
    }
#pragma unroll
    for (int h = 0; h < H; h++)
#pragma unroll
        for (int off = 16; off; off >>= 1)
            s[h] += __shfl_xor_sync(0xffffffffu, s[h], off);

    // pass 3: weighted feature accumulation (warp walks edges together,
    //         lanes cover channels; 128B-coalesced gathers from L2-resident h)
    float acc[H];
#pragma unroll
    for (int h = 0; h < H; h++) acc[h] = 0.f;
    for (int e = beg; e < end; e++) {
        int src = g_col[e];
        const float4* ap4 = (const float4*)(asrc + (size_t)src * H);
        const float*  hp  = hfeat + (size_t)src * (H * 32);
        float av[H];
#pragma unroll
        for (int q = 0; q < H / 4; q++) {
            float4 t = ap4[q];
            av[4 * q] = t.x; av[4 * q + 1] = t.y; av[4 * q + 2] = t.z; av[4 * q + 3] = t.w;
        }
#pragma unroll
        for (int h = 0; h < H; h++) {
            float x = av[h] + ad[h];
            x = x > 0.f ? x : 0.2f * x;
            float wt = __expf(x - m[h]);
            acc[h] += hp[h * 32 + lane] * wt;
        }
    }

    if (MEAN_OUT) {
        float v = 0.f;
#pragma unroll
        for (int h = 0; h < H; h++) v += acc[h] / s[h];
        out[(size_t)w * 32 + lane] = v * (1.f / H) + bias[lane];
    } else {
#pragma unroll
        for (int h = 0; h < H; h++) {
            float v = acc[h] / s[h] + bias[h * 32 + lane];
            if (ELU_OUT) v = v > 0.f ? v : expm1f(v);
            out[(size_t)w * (H * 32) + h * 32 + lane] = v;
        }
    }
}

// ---------------- launch ------------------------------------------------------
extern "C" void kernel_launch(void* const* d_in, const int* in_sizes, int n_in,
                              void* d_out, int out_size) {
    const float* x   = (const float*)d_in[0];
    const void*  ei  = d_in[1];
    const float* W1  = (const float*)d_in[2];
    const float* at_s1 = (const float*)d_in[3];
    const float* at_d1 = (const float*)d_in[4];
    const float* b1  = (const float*)d_in[5];
    const float* W2  = (const float*)d_in[6];
    const float* at_s2 = (const float*)d_in[7];
    const float* at_d2 = (const float*)d_in[8];
    const float* b2  = (const float*)d_in[9];
    float* out = (float*)d_out;

    float *h1, *h1a, *h2, *pas1, *pad1, *pas2, *pad2;
    cudaGetSymbolAddress((void**)&h1,  g_h1);
    cudaGetSymbolAddress((void**)&h1a, g_h1a);
    cudaGetSymbolAddress((void**)&h2,  g_h2);
    cudaGetSymbolAddress((void**)&pas1, g_as1);
    cudaGetSymbolAddress((void**)&pad1, g_ad1);
    cudaGetSymbolAddress((void**)&pas2, g_as2);
    cudaGetSymbolAddress((void**)&pad2, g_ad2);

    // CSR build (sorted-by-destination adjacency, self loops appended)
    detect64_kernel<<<1, 256>>>((const unsigned int*)ei);
    zero_cnt_kernel<<<(N_NODES + 255) / 256, 256>>>();
    count_kernel<<<(E_TOT + 255) / 256, 256>>>(ei);
    scan_kernel<<<1, 1024>>>();
    scatter_kernel<<<(E_TOT + 255) / 256, 256>>>(ei);

    // layer 1
    {
        dim3 grid(128 / BN, (N_NODES + BM - 1) / BM);
        sgemm_kernel<<<grid, 256>>>(x, W1, h1, N_NODES, 128, 128);
    }
    alpha_kernel<4><<<(N_NODES * 4 + 255) / 256, 256>>>(h1, at_s1, at_d1, pas1, pad1);
    gat_edge_kernel<4, true, false><<<(N_NODES + 7) / 8, 256>>>(h1, pas1, pad1, b1, h1a);

    // layer 2
    {
        dim3 grid(256 / BN, (N_NODES + BM - 1) / BM);
        sgemm_kernel<<<grid, 256>>>(h1a, W2, h2, N_NODES, 256, 128);
    }
    alpha_kernel<8><<<(N_NODES * 8 + 255) / 256, 256>>>(h2, at_s2, at_d2, pas2, pad2);
    gat_edge_kernel<8, false, true><<<(N_NODES + 7) / 8, 256>>>(h2, pas2, pad2, b2, out);
}

// round 4
// speedup vs baseline: 1.1472x; 1.1472x over previous
#include <cuda_runtime.h>
#include <math.h>

// Problem constants (fixed by the dataset)
#define N_NODES 50000
#define E_EDGES 800000
#define E_TOT   (E_EDGES + N_NODES)
#define SCAN_NB ((N_NODES + 1023) / 1024)   // 49

// ---------------- scratch (static __device__ allocations only) ----------------
__device__ float g_h1 [(size_t)N_NODES * 128];   // x @ W1            [N,4,32]
__device__ float g_h1a[(size_t)N_NODES * 128];   // elu(gat1 output)  [N,128]
__device__ float g_h2 [(size_t)N_NODES * 256];   // h1a @ W2          [N,8,32]
__device__ float g_as1[N_NODES * 4];
__device__ float g_ad1[N_NODES * 4];
__device__ float g_as2[N_NODES * 8];
__device__ float g_ad2[N_NODES * 8];
__device__ int   g_cnt[N_NODES];
__device__ int   g_tmp[N_NODES];
__device__ int   g_bsum[SCAN_NB];
__device__ int   g_boff[SCAN_NB];
__device__ int   g_rowptr[N_NODES + 1];
__device__ int   g_cursor[N_NODES];
__device__ int   g_col[E_TOT];
__device__ int   g_is64;

// ---------------- dtype detection for edge_index (int64 vs int32) -------------
__global__ void detect64_kernel(const unsigned int* __restrict__ w) {
    __shared__ int any;
    if (threadIdx.x == 0) any = 0;
    __syncthreads();
    // If int64 (little-endian) with values < 2^31, all odd words are 0.
    for (int i = 1 + 2 * threadIdx.x; i < 2048; i += 2 * blockDim.x)
        if (w[i] != 0u) any = 1;   // benign race
    __syncthreads();
    if (threadIdx.x == 0) g_is64 = (any == 0) ? 1 : 0;
}

__global__ void zero_cnt_kernel() {
    int i = blockIdx.x * blockDim.x + threadIdx.x;
    if (i < N_NODES) g_cnt[i] = 0;
}

__global__ void count_kernel(const void* __restrict__ ei) {
    int e = blockIdx.x * blockDim.x + threadIdx.x;
    if (e >= E_TOT) return;
    int dst;
    if (e < E_EDGES) {
        if (g_is64) dst = (int)((const long long*)ei)[(size_t)E_EDGES + e];
        else        dst = ((const int*)ei)[E_EDGES + e];
    } else {
        dst = e - E_EDGES;   // self loop
    }
    atomicAdd(&g_cnt[dst], 1);
}

// ---------------- multi-block scan (3 tiny kernels) ---------------------------
// scan1: per-block (1024 elems) inclusive scan via warp shuffles
__global__ void scan1_kernel() {
    int b = blockIdx.x, tid = threadIdx.x;
    int i = b * 1024 + tid;
    int lane = tid & 31, wid = tid >> 5;
    int v = (i < N_NODES) ? g_cnt[i] : 0;
    int x = v;
#pragma unroll
    for (int off = 1; off < 32; off <<= 1) {
        int t = __shfl_up_sync(0xffffffffu, x, off);
        if (lane >= off) x += t;
    }
    __shared__ int wsum[32];
    if (lane == 31) wsum[wid] = x;
    __syncthreads();
    if (wid == 0) {
        int y = wsum[lane];
#pragma unroll
        for (int off = 1; off < 32; off <<= 1) {
            int t = __shfl_up_sync(0xffffffffu, y, off);
            if (lane >= off) y += t;
        }
        wsum[lane] = y;
    }
    __syncthreads();
    int incl = x + (wid ? wsum[wid - 1] : 0);
    if (i < N_NODES) g_tmp[i] = incl;
    if (tid == 1023) g_bsum[b] = incl;
}

// scan2: exclusive scan of 49 block sums (trivial)
__global__ void scan2_kernel() {
    if (threadIdx.x == 0) {
        int run = 0;
#pragma unroll 1
        for (int j = 0; j < SCAN_NB; j++) { g_boff[j] = run; run += g_bsum[j]; }
        g_rowptr[0] = 0;
    }
}

// scan3: add block offsets, emit rowptr + cursor
__global__ void scan3_kernel() {
    int i = blockIdx.x * blockDim.x + threadIdx.x;
    if (i >= N_NODES) return;
    int incl = g_tmp[i] + g_boff[i >> 10];
    g_rowptr[i + 1] = incl;
    g_cursor[i]     = incl - g_cnt[i];
}

__global__ void scatter_kernel(const void* __restrict__ ei) {
    int e = blockIdx.x * blockDim.x + threadIdx.x;
    if (e >= E_TOT) return;
    int src, dst;
    if (e < E_EDGES) {
        if (g_is64) {
            const long long* p = (const long long*)ei;
            src = (int)p[e];
            dst = (int)p[(size_t)E_EDGES + e];
        } else {
            const int* p = (const int*)ei;
            src = p[e];
            dst = p[E_EDGES + e];
        }
    } else {
        src = dst = e - E_EDGES;
    }
    int pos = atomicAdd(&g_cursor[dst], 1);
    g_col[pos] = src;
}

// ---------------- SGEMM: C[M,Ncols] = A[M,K] @ B[K,Ncols] ---------------------
// 64x64 tile, 256 threads, 4x4 per-thread register tile, BK=16.
#define BM 64
#define BN 64
#define BK 16
__global__ void sgemm_kernel(const float* __restrict__ A,
                             const float* __restrict__ B,
                             float* __restrict__ C,
                             int M, int Ncols, int K) {
    __shared__ float As[BK][BM];
    __shared__ float Bs[BK][BN];
    int tid = threadIdx.x;
    int row0 = blockIdx.y * BM;
    int col0 = blockIdx.x * BN;
    int ty = tid / 16, tx = tid % 16;

    int arow = tid / 4;          // 0..63
    int acol = (tid % 4) * 4;    // 0,4,8,12
    int brw  = tid / 16;         // 0..15
    int bcl  = (tid % 16) * 4;   // 0..60

    float acc[4][4];
#pragma unroll
    for (int i = 0; i < 4; i++)
#pragma unroll
        for (int j = 0; j < 4; j++) acc[i][j] = 0.f;

    for (int k0 = 0; k0 < K; k0 += BK) {
        float4 av = make_float4(0.f, 0.f, 0.f, 0.f);
        if (row0 + arow < M)
            av = *(const float4*)(A + (size_t)(row0 + arow) * K + k0 + acol);
        As[acol + 0][arow] = av.x;
        As[acol + 1][arow] = av.y;
        As[acol + 2][arow] = av.z;
        As[acol + 3][arow] = av.w;
        float4 bv = *(const float4*)(B + (size_t)(k0 + brw) * Ncols + col0 + bcl);
        *(float4*)&Bs[brw][bcl] = bv;
        __syncthreads();
#pragma unroll
        for (int kk = 0; kk < BK; kk++) {
            float4 a = *(float4*)&As[kk][ty * 4];
            float4 b = *(float4*)&Bs[kk][tx * 4];
            acc[0][0] += a.x * b.x; acc[0][1] += a.x * b.y; acc[0][2] += a.x * b.z; acc[0][3] += a.x * b.w;
            acc[1][0] += a.y * b.x; acc[1][1] += a.y * b.y; acc[1][2] += a.y * b.z; acc[1][3] += a.y * b.w;
            acc[2][0] += a.z * b.x; acc[2][1] += a.z * b.y; acc[2][2] += a.z * b.z; acc[2][3] += a.z * b.w;
            acc[3][0] += a.w * b.x; acc[3][1] += a.w * b.y; acc[3][2] += a.w * b.z; acc[3][3] += a.w * b.w;
        }
        __syncthreads();
    }
#pragma unroll
    for (int i = 0; i < 4; i++) {
        int r = row0 + ty * 4 + i;
        if (r < M)
            *(float4*)(C + (size_t)r * Ncols + col0 + tx * 4) =
                make_float4(acc[i][0], acc[i][1], acc[i][2], acc[i][3]);
    }
}

// ---------------- per-node attention coefficients -----------------------------
template <int H>
__global__ void alpha_kernel(const float* __restrict__ h,
                             const float* __restrict__ att_s,
                             const float* __restrict__ att_d,
                             float* __restrict__ as_out,
                             float* __restrict__ ad_out) {
    int idx = blockIdx.x * blockDim.x + threadIdx.x;
    if (idx >= N_NODES * H) return;
    int node = idx / H, hh = idx % H;
    const float* hp = h + (size_t)node * H * 32 + hh * 32;
    const float* a1 = att_s + hh * 32;
    const float* a2 = att_d + hh * 32;
    float s1 = 0.f, s2 = 0.f;
#pragma unroll
    for (int c = 0; c < 32; c += 4) {
        float4 v  = *(const float4*)(hp + c);
        float4 w1 = *(const float4*)(a1 + c);
        float4 w2 = *(const float4*)(a2 + c);
        s1 += v.x * w1.x + v.y * w1.y + v.z * w1.z + v.w * w1.w;
        s2 += v.x * w2.x + v.y * w2.y + v.z * w2.z + v.w * w2.w;
    }
    as_out[idx] = s1;
    ad_out[idx] = s2;
}

// ---------------- GAT edge aggregation: one warp per destination node ---------
// Channels C=32 map to lanes; heads H map to the per-lane register index.
// Pass A: ONLINE softmax (max+sum fused, one expf/edge). Pass B: accumulate.
template <int H, bool ELU_OUT, bool MEAN_OUT>
__global__ void gat_edge_kernel(const float* __restrict__ hfeat,
                                const float* __restrict__ asrc,
                                const float* __restrict__ adst,
                                const float* __restrict__ bias,
                                float* __restrict__ out) {
    int w    = (blockIdx.x * blockDim.x + threadIdx.x) >> 5;
    int lane = threadIdx.x & 31;
    if (w >= N_NODES) return;
    int beg = g_rowptr[w], end = g_rowptr[w + 1];

    float ad[H];
#pragma unroll
    for (int h = 0; h < H; h++) ad[h] = adst[(size_t)w * H + h];

    // pass A: online max + sum over edges (lane-parallel)
    float m[H], s[H];
#pragma unroll
    for (int h = 0; h < H; h++) { m[h] = -1e30f; s[h] = 0.f; }
    for (int e = beg + lane; e < end; e += 32) {
        int src = g_col[e];
        const float4* ap4 = (const float4*)(asrc + (size_t)src * H);
        float av[H];
#pragma unroll
        for (int q = 0; q < H / 4; q++) {
            float4 t = ap4[q];
            av[4 * q] = t.x; av[4 * q + 1] = t.y; av[4 * q + 2] = t.z; av[4 * q + 3] = t.w;
        }
#pragma unroll
        for (int h = 0; h < H; h++) {
            float x = av[h] + ad[h];
            x = x > 0.f ? x : 0.2f * x;
            if (x > m[h]) {
                s[h] = s[h] * __expf(m[h] - x) + 1.f;
                m[h] = x;
            } else {
                s[h] += __expf(x - m[h]);
            }
        }
    }
    // merge lanes: global max, rescale sums, reduce
#pragma unroll
    for (int h = 0; h < H; h++) {
        float mw = m[h];
#pragma unroll
        for (int off = 16; off; off >>= 1)
            mw = fmaxf(mw, __shfl_xor_sync(0xffffffffu, mw, off));
        float sw = s[h] * __expf(m[h] - mw);
#pragma unroll
        for (int off = 16; off; off >>= 1)
            sw += __shfl_xor_sync(0xffffffffu, sw, off);
        m[h] = mw;
        s[h] = sw;
    }

    // pass B: weighted feature accumulation (warp walks edges together,
    //         lanes cover channels; 128B-coalesced gathers from L2-resident h)
    float acc[H];
#pragma unroll
    for (int h = 0; h < H; h++) acc[h] = 0.f;
    for (int e = beg; e < end; e++) {
        int src = g_col[e];
        const float4* ap4 = (const float4*)(asrc + (size_t)src * H);
        const float*  hp  = hfeat + (size_t)src * (H * 32);
        float av[H];
#pragma unroll
        for (int q = 0; q < H / 4; q++) {
            float4 t = ap4[q];
            av[4 * q] = t.x; av[4 * q + 1] = t.y; av[4 * q + 2] = t.z; av[4 * q + 3] = t.w;
        }
#pragma unroll
        for (int h = 0; h < H; h++) {
            float x = av[h] + ad[h];
            x = x > 0.f ? x : 0.2f * x;
            float wt = __expf(x - m[h]);
            acc[h] += hp[h * 32 + lane] * wt;
        }
    }

    if (MEAN_OUT) {
        float v = 0.f;
#pragma unroll
        for (int h = 0; h < H; h++) v += acc[h] / s[h];
        out[(size_t)w * 32 + lane] = v * (1.f / H) + bias[lane];
    } else {
#pragma unroll
        for (int h = 0; h < H; h++) {
            float v = acc[h] / s[h] + bias[h * 32 + lane];
            if (ELU_OUT) v = v > 0.f ? v : expm1f(v);
            out[(size_t)w * (H * 32) + h * 32 + lane] = v;
        }
    }
}

// ---------------- launch ------------------------------------------------------
extern "C" void kernel_launch(void* const* d_in, const int* in_sizes, int n_in,
                              void* d_out, int out_size) {
    const float* x   = (const float*)d_in[0];
    const void*  ei  = d_in[1];
    const float* W1  = (const float*)d_in[2];
    const float* at_s1 = (const float*)d_in[3];
    const float* at_d1 = (const float*)d_in[4];
    const float* b1  = (const float*)d_in[5];
    const float* W2  = (const float*)d_in[6];
    const float* at_s2 = (const float*)d_in[7];
    const float* at_d2 = (const float*)d_in[8];
    const float* b2  = (const float*)d_in[9];
    float* out = (float*)d_out;

    float *h1, *h1a, *h2, *pas1, *pad1, *pas2, *pad2;
    cudaGetSymbolAddress((void**)&h1,  g_h1);
    cudaGetSymbolAddress((void**)&h1a, g_h1a);
    cudaGetSymbolAddress((void**)&h2,  g_h2);
    cudaGetSymbolAddress((void**)&pas1, g_as1);
    cudaGetSymbolAddress((void**)&pad1, g_ad1);
    cudaGetSymbolAddress((void**)&pas2, g_as2);
    cudaGetSymbolAddress((void**)&pad2, g_ad2);

    // CSR build (sorted-by-destination adjacency, self loops appended)
    detect64_kernel<<<1, 256>>>((const unsigned int*)ei);
    zero_cnt_kernel<<<(N_NODES + 255) / 256, 256>>>();
    count_kernel<<<(E_TOT + 255) / 256, 256>>>(ei);
    scan1_kernel<<<SCAN_NB, 1024>>>();
    scan2_kernel<<<1, 32>>>();
    scan3_kernel<<<(N_NODES + 255) / 256, 256>>>();
    scatter_kernel<<<(E_TOT + 255) / 256, 256>>>(ei);

    // layer 1
    {
        dim3 grid(128 / BN, (N_NODES + BM - 1) / BM);
        sgemm_kernel<<<grid, 256>>>(x, W1, h1, N_NODES, 128, 128);
    }
    alpha_kernel<4><<<(N_NODES * 4 + 255) / 256, 256>>>(h1, at_s1, at_d1, pas1, pad1);
    gat_edge_kernel<4, true, false><<<(N_NODES + 7) / 8, 256>>>(h1, pas1, pad1, b1, h1a);

    // layer 2
    {
        dim3 grid(256 / BN, (N_NODES + BM - 1) / BM);
        sgemm_kernel<<<grid, 256>>>(h1a, W2, h2, N_NODES, 256, 128);
    }
    alpha_kernel<8><<<(N_NODES * 8 + 255) / 256, 256>>>(h2, at_s2, at_d2, pas2, pad2);
    gat_edge_kernel<8, false, true><<<(N_NODES + 7) / 8, 256>>>(h2, pas2, pad2, b2, out);
}